// round 8
// baseline (speedup 1.0000x reference)
#include <cuda_runtime.h>
#include <cuda_fp16.h>
#include <cstdint>

#define NB  16
#define NC  512
#define NK  512
#define NHW 4096
#define NP  (NB * NHW)   // 65536 pixels

// --------------------------------------------------------------------------
// Allocation-free scratch
// --------------------------------------------------------------------------
__device__ __half g_xh[(size_t)NP * NC];   // x hi-limb, [p][c] K-major
__device__ __half g_xl[(size_t)NP * NC];   // x lo-limb
__device__ __half g_ch[NK * NC];           // centers hi-limb [k][c]
__device__ __half g_cl[NK * NC];           // centers lo-limb
__device__ float  g_csq[NK];
__device__ unsigned long long g_part[(size_t)NP * 4];

// --------------------------------------------------------------------------
// Prep kernels
// --------------------------------------------------------------------------
__global__ void convert_c(const float* __restrict__ cent) {
    int idx = blockIdx.x * 256 + threadIdx.x;
    if (idx < NK * NC) {
        float f   = cent[idx];
        __half hi = __float2half_rn(f);
        g_ch[idx] = hi;
        g_cl[idx] = __float2half_rn(f - __half2float(hi));
    }
}

__global__ void csq_kernel(const float* __restrict__ cent) {
    __shared__ double red[128];
    const int k = blockIdx.x;
    const int t = threadIdx.x;
    double s = 0.0;
    #pragma unroll
    for (int i = 0; i < 4; ++i) {
        double v = (double)cent[k * NC + t + i * 128];
        s += v * v;
    }
    red[t] = s;
    __syncthreads();
    for (int off = 64; off > 0; off >>= 1) {
        if (t < off) red[t] += red[t + off];
        __syncthreads();
    }
    if (t == 0) g_csq[k] = (float)red[0];
}

// x (B,C,H,W) fp32 -> [p][c] fp16 limbs via smem transpose
__global__ void convert_x(const float* __restrict__ x) {
    __shared__ float s[64][65];
    const int p0 = blockIdx.x * 64;
    const int c0 = blockIdx.y * 64;
    const int b   = p0 >> 12;
    const int hw0 = p0 & 4095;
    const int t = threadIdx.x;
    const float* src = x + (size_t)b * NC * NHW + hw0;

    #pragma unroll
    for (int i = 0; i < 4; ++i) {
        int cl = i * 16 + (t >> 4);
        int pl = (t & 15) * 4;
        float4 v = *reinterpret_cast<const float4*>(src + (size_t)(c0 + cl) * NHW + pl);
        s[cl][pl] = v.x; s[cl][pl + 1] = v.y; s[cl][pl + 2] = v.z; s[cl][pl + 3] = v.w;
    }
    __syncthreads();

    #pragma unroll
    for (int i = 0; i < 4; ++i) {
        int pl = i * 16 + (t >> 4);
        int c4 = (t & 15) * 4;
        __half h[4], l[4];
        #pragma unroll
        for (int k2 = 0; k2 < 4; ++k2) {
            float f   = s[c4 + k2][pl];
            __half hi = __float2half_rn(f);
            h[k2] = hi;
            l[k2] = __float2half_rn(f - __half2float(hi));
        }
        __half2 h01 = __halves2half2(h[0], h[1]), h23 = __halves2half2(h[2], h[3]);
        __half2 l01 = __halves2half2(l[0], l[1]), l23 = __halves2half2(l[2], l[3]);
        uint2 uh, ul;
        uh.x = *reinterpret_cast<unsigned*>(&h01); uh.y = *reinterpret_cast<unsigned*>(&h23);
        ul.x = *reinterpret_cast<unsigned*>(&l01); ul.y = *reinterpret_cast<unsigned*>(&l23);
        size_t off = (size_t)(p0 + pl) * NC + c0 + c4;
        *reinterpret_cast<uint2*>(&g_xh[off]) = uh;
        *reinterpret_cast<uint2*>(&g_xl[off]) = ul;
    }
}

// --------------------------------------------------------------------------
// Helpers
// --------------------------------------------------------------------------
__device__ __forceinline__ uint32_t smem_u32(const void* p) {
    uint32_t a;
    asm("{ .reg .u64 t; cvta.to.shared.u64 t, %1; cvt.u32.u64 %0, t; }"
        : "=r"(a) : "l"(p));
    return a;
}
__device__ __forceinline__ unsigned long long enc_key(float v, int k) {
    unsigned u = __float_as_uint(v);
    u = (u & 0x80000000u) ? ~u : (u | 0x80000000u);
    return ((unsigned long long)u << 32) | (unsigned)k;
}
__device__ __forceinline__ void ldmx4(uint32_t* r, uint32_t addr) {
    asm volatile("ldmatrix.sync.aligned.m8n8.x4.shared.b16 {%0,%1,%2,%3}, [%4];"
                 : "=r"(r[0]), "=r"(r[1]), "=r"(r[2]), "=r"(r[3]) : "r"(addr));
}
__device__ __forceinline__ void mma16816(float* d, const uint32_t* a,
                                         uint32_t b0, uint32_t b1) {
    asm volatile(
        "mma.sync.aligned.m16n8k16.row.col.f32.f16.f16.f32 "
        "{%0,%1,%2,%3}, {%4,%5,%6,%7}, {%8,%9}, {%0,%1,%2,%3};"
        : "+f"(d[0]), "+f"(d[1]), "+f"(d[2]), "+f"(d[3])
        : "r"(a[0]), "r"(a[1]), "r"(a[2]), "r"(a[3]), "r"(b0), "r"(b1));
}

// --------------------------------------------------------------------------
// Smem: 3 stages x 32 KB (A 16 KB: 2 limbs x 128 px x 64 B; B same for codes)
// 64 B rows, XOR swizzle j ^= (row>>1)&3 on 16 B units. EPI overlays stages.
// --------------------------------------------------------------------------
#define STG_BYTES 32768
#define B_OFF     16384
#define LIMB_OFF  8192
#define OFF_CSQ   98304
#define SMEM_TOTAL 98816

// --------------------------------------------------------------------------
// Main GEMM: CTA = 128 px x 128 codes; 16 stages of 32 channels.
// Pure cp.async -> ldmatrix -> mma.sync mainloop; 1 sync / iter; 3-stage ring.
// --------------------------------------------------------------------------
__global__ __launch_bounds__(256, 2)
void hmma_argmin(int dummy) {
    extern __shared__ __align__(1024) char smem[];
    const uint32_t sb = smem_u32(smem);
    const int tid  = threadIdx.x;
    const int lane = tid & 31;
    const int wid  = tid >> 5;
    const int wm   = wid >> 2;     // 0..1 : 64-px block
    const int wn   = wid & 3;      // 0..3 : 32-code block

    const int grp = blockIdx.x >> 2;
    const int kc  = blockIdx.x & 3;
    const int p0  = grp * 128;

    float* cs = (float*)(smem + OFF_CSQ);
    if (tid < 128) cs[tid] = g_csq[kc * 128 + tid];

    // ---- stage loader: 2048 x 16B cp.async (8 per thread) ----
    auto load_stage = [&](int i) {
        const int c0  = i << 5;
        const int stg = i % 3;
        #pragma unroll
        for (int u = 0; u < 8; ++u) {
            int q    = tid + (u << 8);          // 0..2047
            int ab   = q >> 10;                 // 0=A(x), 1=B(centers)
            int limb = (q >> 9) & 1;
            int row  = (q >> 2) & 127;
            int j    = q & 3;
            const __half* src = ab
                ? (limb ? g_cl : g_ch) + (size_t)(kc * 128 + row) * NC + c0 + j * 8
                : (limb ? g_xl : g_xh) + (size_t)(p0 + row) * NC + c0 + j * 8;
            uint32_t dst = sb + stg * STG_BYTES + ab * B_OFF + limb * LIMB_OFF
                           + row * 64 + ((j ^ ((row >> 1) & 3)) << 4);
            asm volatile("cp.async.cg.shared.global [%0], [%1], 16;"
                         :: "r"(dst), "l"(src) : "memory");
        }
        asm volatile("cp.async.commit_group;" ::: "memory");
    };

    float acc[4][4][4];
    #pragma unroll
    for (int m = 0; m < 4; ++m)
        #pragma unroll
        for (int n = 0; n < 4; ++n)
            #pragma unroll
            for (int r = 0; r < 4; ++r) acc[m][n][r] = 0.0f;

    // per-lane ldmatrix row bases + swizzle (mt/nt row steps of 16 keep sw const)
    const int rA  = wm * 64 + (lane & 15);
    const int swA = (rA >> 1) & 3;
    const int rB  = wn * 32 + (lane & 15);
    const int swB = (rB >> 1) & 3;
    const int khalf = lane >> 4;

    auto compute = [&](int stg) {
        const uint32_t Ab = sb + stg * STG_BYTES;
        const uint32_t Bb = Ab + B_OFF;
        #pragma unroll
        for (int ks = 0; ks < 2; ++ks) {
            const int jj = ks * 2 + khalf;
            uint32_t ah[4][4], al[4][4];
            #pragma unroll
            for (int mt = 0; mt < 4; ++mt) {
                uint32_t a = Ab + (rA + mt * 16) * 64 + ((jj ^ swA) << 4);
                ldmx4(ah[mt], a);
                ldmx4(al[mt], a + LIMB_OFF);
            }
            #pragma unroll
            for (int nt = 0; nt < 2; ++nt) {
                uint32_t bh[4], bl[4];
                uint32_t bAddr = Bb + (rB + nt * 16) * 64 + ((jj ^ swB) << 4);
                ldmx4(bh, bAddr);
                ldmx4(bl, bAddr + LIMB_OFF);
                #pragma unroll
                for (int sub = 0; sub < 2; ++sub) {
                    const int nn = nt * 2 + sub;
                    const uint32_t bh0 = bh[sub], bh1 = bh[sub + 2];
                    const uint32_t bl0 = bl[sub], bl1 = bl[sub + 2];
                    #pragma unroll
                    for (int mt = 0; mt < 4; ++mt) {
                        mma16816(acc[mt][nn], ah[mt], bh0, bh1);
                        mma16816(acc[mt][nn], ah[mt], bl0, bl1);
                        mma16816(acc[mt][nn], al[mt], bh0, bh1);
                    }
                }
            }
        }
    };

    // ---- 3-stage pipeline, one barrier per iteration ----
    load_stage(0);
    load_stage(1);
    #pragma unroll 1
    for (int i = 0; i < 16; ++i) {
        if (i + 2 < 16) asm volatile("cp.async.wait_group 1;" ::: "memory");
        else            asm volatile("cp.async.wait_group 0;" ::: "memory");
        __syncthreads();                 // stage i ready; all warps done with i-1
        if (i + 2 < 16) load_stage(i + 2);   // overwrites buf (i-1)%3: safe
        compute(i % 3);
    }
    __syncthreads();                     // all compute done before EPI overlay

    // ---- epilogue: spill 128x128 fp32, fused argmin ----
    float* epi = (float*)smem;
    const int r4 = lane >> 2, c2 = (lane & 3) << 1;
    #pragma unroll
    for (int mt = 0; mt < 4; ++mt)
        #pragma unroll
        for (int nn = 0; nn < 4; ++nn) {
            const int row = wm * 64 + mt * 16 + r4;
            const int col = wn * 32 + nn * 8 + c2;
            *(float2*)(epi + row * 128 + col)       = make_float2(acc[mt][nn][0], acc[mt][nn][1]);
            *(float2*)(epi + (row + 8) * 128 + col) = make_float2(acc[mt][nn][2], acc[mt][nn][3]);
        }
    __syncthreads();

    const int row  = tid >> 1;
    const int half = tid & 1;
    const float* er = epi + row * 128 + half * 64;
    unsigned long long bl = ~0ULL;
    #pragma unroll 8
    for (int j = 0; j < 64; ++j) {
        int kg  = kc * 128 + half * 64 + j;
        float v = fmaf(-2.0f, er[j], cs[half * 64 + j]);
        unsigned long long e = enc_key(v, kg);
        if (e < bl) bl = e;
    }
    unsigned long long other = __shfl_xor_sync(0xFFFFFFFFu, bl, 1);
    if (other < bl) bl = other;
    if (half == 0)
        g_part[(size_t)(p0 + row) * 4 + kc] = bl;
    (void)dummy;
}

// --------------------------------------------------------------------------
// Finalize: min across 4 chunks per pixel -> float index
// --------------------------------------------------------------------------
__global__ void finalize(float* __restrict__ out) {
    int p = blockIdx.x * 256 + threadIdx.x;
    const unsigned long long* q = &g_part[(size_t)p * 4];
    unsigned long long m = q[0];
    unsigned long long v1 = q[1], v2 = q[2], v3 = q[3];
    if (v1 < m) m = v1;
    if (v2 < m) m = v2;
    if (v3 < m) m = v3;
    out[p] = (float)(int)(unsigned)(m & 0xFFFFFFFFULL);
}

// --------------------------------------------------------------------------
// Launch
// --------------------------------------------------------------------------
extern "C" void kernel_launch(void* const* d_in, const int* in_sizes, int n_in,
                              void* d_out, int out_size) {
    const float* x    = (const float*)d_in[0];
    const float* cent = (const float*)d_in[1];
    if (n_in >= 2 && in_sizes[0] < in_sizes[1]) {
        const float* t = x; x = cent; cent = t;
    }

    cudaFuncSetAttribute(hmma_argmin,
                         cudaFuncAttributeMaxDynamicSharedMemorySize, SMEM_TOTAL);

    convert_c<<<(NK * NC + 255) / 256, 256>>>(cent);
    csq_kernel<<<NK, 128>>>(cent);
    dim3 tg(NP / 64, NC / 64);
    convert_x<<<tg, 256>>>(x);
    hmma_argmin<<<NP / 128 * 4, 256, SMEM_TOTAL>>>(0);
    finalize<<<NP / 256, 256>>>((float*)d_out);
    (void)out_size;
}

// round 9
// speedup vs baseline: 1.3757x; 1.3757x over previous
#include <cuda_runtime.h>
#include <cuda_fp16.h>
#include <cstdint>

#define NB  16
#define NC  512
#define NK  512
#define NHW 4096
#define NP  (NB * NHW)   // 65536 pixels

#define RESCUE_T 0.5f

// --------------------------------------------------------------------------
// Allocation-free scratch
// --------------------------------------------------------------------------
__device__ __half g_x16[(size_t)NP * NC];   // x fp16, [p][c] K-major
__device__ __half g_c16[NK * NC];           // centers fp16 [k][c]
__device__ float  g_centT[NC * NK];         // centers fp32 transposed [c][k]
__device__ float  g_csq[NK];
__device__ unsigned long long g_partk[(size_t)NP * 4];  // per-(pixel,chunk) min key
__device__ float              g_partv[(size_t)NP * 4];  // per-(pixel,chunk) 2nd-min val
__device__ int g_count;
__device__ int g_queue[NP];

// --------------------------------------------------------------------------
// Helpers
// --------------------------------------------------------------------------
__device__ __forceinline__ uint32_t smem_u32(const void* p) {
    uint32_t a;
    asm("{ .reg .u64 t; cvta.to.shared.u64 t, %1; cvt.u32.u64 %0, t; }"
        : "=r"(a) : "l"(p));
    return a;
}
__device__ __forceinline__ unsigned long long enc_key(float v, int k) {
    unsigned u = __float_as_uint(v);
    u = (u & 0x80000000u) ? ~u : (u | 0x80000000u);
    return ((unsigned long long)u << 32) | (unsigned)k;
}
__device__ __forceinline__ float key_val(unsigned long long key) {
    unsigned u = (unsigned)(key >> 32);
    unsigned b = (u & 0x80000000u) ? (u & 0x7FFFFFFFu) : ~u;
    return __uint_as_float(b);
}
// top-2 merge: (k1,v2) <- merge of (k1,v2) and (ok1,ov2)
__device__ __forceinline__ void t2merge(unsigned long long& k1, float& v2,
                                        unsigned long long ok1, float ov2) {
    if (ok1 < k1) { v2 = fminf(key_val(k1), ov2); k1 = ok1; }
    else          { v2 = fminf(v2, key_val(ok1)); }
}
__device__ __forceinline__ void ldmx4(uint32_t* r, uint32_t addr) {
    asm volatile("ldmatrix.sync.aligned.m8n8.x4.shared.b16 {%0,%1,%2,%3}, [%4];"
                 : "=r"(r[0]), "=r"(r[1]), "=r"(r[2]), "=r"(r[3]) : "r"(addr));
}
__device__ __forceinline__ void mma16816(float* d, const uint32_t* a,
                                         uint32_t b0, uint32_t b1) {
    asm volatile(
        "mma.sync.aligned.m16n8k16.row.col.f32.f16.f16.f32 "
        "{%0,%1,%2,%3}, {%4,%5,%6,%7}, {%8,%9}, {%0,%1,%2,%3};"
        : "+f"(d[0]), "+f"(d[1]), "+f"(d[2]), "+f"(d[3])
        : "r"(a[0]), "r"(a[1]), "r"(a[2]), "r"(a[3]), "r"(b0), "r"(b1));
}

// --------------------------------------------------------------------------
// Prep kernels
// --------------------------------------------------------------------------
__global__ void convert_c(const float* __restrict__ cent) {
    int idx = blockIdx.x * 256 + threadIdx.x;
    if (idx == 0) g_count = 0;
    if (idx < NK * NC) {
        float f = cent[idx];
        g_c16[idx] = __float2half_rn(f);
        int k = idx >> 9, c = idx & 511;
        g_centT[c * NK + k] = f;
    }
}

__global__ void csq_kernel(const float* __restrict__ cent) {
    __shared__ double red[128];
    const int k = blockIdx.x;
    const int t = threadIdx.x;
    double s = 0.0;
    #pragma unroll
    for (int i = 0; i < 4; ++i) {
        double v = (double)cent[k * NC + t + i * 128];
        s += v * v;
    }
    red[t] = s;
    __syncthreads();
    for (int off = 64; off > 0; off >>= 1) {
        if (t < off) red[t] += red[t + off];
        __syncthreads();
    }
    if (t == 0) g_csq[k] = (float)red[0];
}

// x (B,C,H,W) fp32 -> [p][c] fp16 via smem transpose
__global__ void convert_x(const float* __restrict__ x) {
    __shared__ float s[64][65];
    const int p0 = blockIdx.x * 64;
    const int c0 = blockIdx.y * 64;
    const int b   = p0 >> 12;
    const int hw0 = p0 & 4095;
    const int t = threadIdx.x;
    const float* src = x + (size_t)b * NC * NHW + hw0;

    #pragma unroll
    for (int i = 0; i < 4; ++i) {
        int cl = i * 16 + (t >> 4);
        int pl = (t & 15) * 4;
        float4 v = *reinterpret_cast<const float4*>(src + (size_t)(c0 + cl) * NHW + pl);
        s[cl][pl] = v.x; s[cl][pl + 1] = v.y; s[cl][pl + 2] = v.z; s[cl][pl + 3] = v.w;
    }
    __syncthreads();

    #pragma unroll
    for (int i = 0; i < 4; ++i) {
        int pl = i * 16 + (t >> 4);
        int c4 = (t & 15) * 4;
        __half2 h01 = __halves2half2(__float2half_rn(s[c4][pl]),
                                     __float2half_rn(s[c4 + 1][pl]));
        __half2 h23 = __halves2half2(__float2half_rn(s[c4 + 2][pl]),
                                     __float2half_rn(s[c4 + 3][pl]));
        uint2 uh;
        uh.x = *reinterpret_cast<unsigned*>(&h01);
        uh.y = *reinterpret_cast<unsigned*>(&h23);
        *reinterpret_cast<uint2*>(&g_x16[(size_t)(p0 + pl) * NC + c0 + c4]) = uh;
    }
}

// --------------------------------------------------------------------------
// Smem layout for GEMM: 4 stages x 16 KB (A 8 KB + B 8 KB), 64 B rows,
// XOR swizzle on 16 B units. Then csq (512 B) + top2 key (4 KB) + v2 (2 KB).
// --------------------------------------------------------------------------
#define STG_BYTES 16384
#define B_OFF     8192
#define OFF_CSQ   65536
#define OFF_K2    66048
#define OFF_V2    70144
#define SMEM_TOTAL 72192

// --------------------------------------------------------------------------
// Main GEMM: CTA = 128 px x 128 codes (grid 2048 = 512 groups x 4 chunks).
// Single fp16 pass, 16 iters of 32 channels, 4-stage cp.async ring.
// Epilogue: register top-2 per row -> g_partk/g_partv.
// --------------------------------------------------------------------------
__global__ __launch_bounds__(256, 2)
void hmma_top2() {
    extern __shared__ __align__(1024) char smem[];
    const uint32_t sb = smem_u32(smem);
    const int tid  = threadIdx.x;
    const int lane = tid & 31;
    const int wid  = tid >> 5;
    const int wm   = wid >> 2;     // 0..1 : 64-px block
    const int wn   = wid & 3;      // 0..3 : 32-code block

    const int grp = blockIdx.x >> 2;
    const int kc  = blockIdx.x & 3;
    const int p0  = grp * 128;

    float* cs = (float*)(smem + OFF_CSQ);
    if (tid < 128) cs[tid] = g_csq[kc * 128 + tid];

    // ---- stage loader: 1024 x 16B cp.async (4 per thread) ----
    auto load_stage = [&](int i) {
        const int c0  = i << 5;
        const int stg = i & 3;
        #pragma unroll
        for (int u = 0; u < 4; ++u) {
            int q   = tid + (u << 8);           // 0..1023
            int ab  = q >> 9;                   // 0=A(x), 1=B(centers)
            int row = (q >> 2) & 127;
            int j   = q & 3;
            const __half* src = ab
                ? g_c16 + (size_t)(kc * 128 + row) * NC + c0 + j * 8
                : g_x16 + (size_t)(p0 + row) * NC + c0 + j * 8;
            uint32_t dst = sb + stg * STG_BYTES + ab * B_OFF
                           + row * 64 + ((j ^ ((row >> 1) & 3)) << 4);
            asm volatile("cp.async.cg.shared.global [%0], [%1], 16;"
                         :: "r"(dst), "l"(src) : "memory");
        }
        asm volatile("cp.async.commit_group;" ::: "memory");
    };

    float acc[4][4][4];
    #pragma unroll
    for (int m = 0; m < 4; ++m)
        #pragma unroll
        for (int n = 0; n < 4; ++n)
            #pragma unroll
            for (int r = 0; r < 4; ++r) acc[m][n][r] = 0.0f;

    const int rA  = wm * 64 + (lane & 15);
    const int swA = (rA >> 1) & 3;
    const int rB  = wn * 32 + (lane & 15);
    const int swB = (rB >> 1) & 3;
    const int khalf = lane >> 4;

    auto compute = [&](int stg) {
        const uint32_t Ab = sb + stg * STG_BYTES;
        const uint32_t Bb = Ab + B_OFF;
        #pragma unroll
        for (int ks = 0; ks < 2; ++ks) {
            const int jj = ks * 2 + khalf;
            uint32_t ah[4][4];
            #pragma unroll
            for (int mt = 0; mt < 4; ++mt)
                ldmx4(ah[mt], Ab + (rA + mt * 16) * 64 + ((jj ^ swA) << 4));
            #pragma unroll
            for (int nt = 0; nt < 2; ++nt) {
                uint32_t bf[4];
                ldmx4(bf, Bb + (rB + nt * 16) * 64 + ((jj ^ swB) << 4));
                #pragma unroll
                for (int sub = 0; sub < 2; ++sub) {
                    const int nn = nt * 2 + sub;
                    #pragma unroll
                    for (int mt = 0; mt < 4; ++mt)
                        mma16816(acc[mt][nn], ah[mt], bf[sub], bf[sub + 2]);
                }
            }
        }
    };

    // ---- 4-stage pipeline, one barrier per iteration ----
    load_stage(0); load_stage(1); load_stage(2);
    #pragma unroll 1
    for (int i = 0; i < 16; ++i) {
        if (i < 14)      asm volatile("cp.async.wait_group 2;" ::: "memory");
        else if (i == 14) asm volatile("cp.async.wait_group 1;" ::: "memory");
        else              asm volatile("cp.async.wait_group 0;" ::: "memory");
        __syncthreads();               // stage i ready; all warps done with i-1
        if (i + 3 < 16) load_stage(i + 3);
        compute(i & 3);
    }

    // ---- epilogue: per-row top-2 in registers, merge via shfl ----
    unsigned long long* smk = (unsigned long long*)(smem + OFF_K2);
    float*              smv = (float*)(smem + OFF_V2);
    const int r4 = lane >> 2, c2 = (lane & 3) << 1;

    #pragma unroll
    for (int mt = 0; mt < 4; ++mt) {
        unsigned long long k1a = ~0ULL, k1b = ~0ULL;
        float v2a = 3.0e38f, v2b = 3.0e38f;
        const int row0 = wm * 64 + mt * 16 + r4;
        #pragma unroll
        for (int nn = 0; nn < 4; ++nn) {
            #pragma unroll
            for (int cc = 0; cc < 2; ++cc) {
                const int col = wn * 32 + nn * 8 + c2 + cc;
                const int kg  = kc * 128 + col;
                float va = fmaf(-2.0f, acc[mt][nn][cc], cs[col]);
                float vb = fmaf(-2.0f, acc[mt][nn][cc + 2], cs[col]);
                unsigned long long ea = enc_key(va, kg);
                unsigned long long eb = enc_key(vb, kg);
                if (ea < k1a) { v2a = fminf(v2a, key_val(k1a)); k1a = ea; }
                else           v2a = fminf(v2a, va);
                if (eb < k1b) { v2b = fminf(v2b, key_val(k1b)); k1b = eb; }
                else           v2b = fminf(v2b, vb);
            }
        }
        #pragma unroll
        for (int d = 1; d <= 2; d <<= 1) {
            unsigned long long oka = __shfl_xor_sync(0xFFFFFFFFu, k1a, d);
            float ova              = __shfl_xor_sync(0xFFFFFFFFu, v2a, d);
            t2merge(k1a, v2a, oka, ova);
            unsigned long long okb = __shfl_xor_sync(0xFFFFFFFFu, k1b, d);
            float ovb              = __shfl_xor_sync(0xFFFFFFFFu, v2b, d);
            t2merge(k1b, v2b, okb, ovb);
        }
        if ((lane & 3) == 0) {
            smk[row0 * 4 + wn] = k1a;  smv[row0 * 4 + wn] = v2a;
            smk[(row0 + 8) * 4 + wn] = k1b;  smv[(row0 + 8) * 4 + wn] = v2b;
        }
    }
    __syncthreads();

    if (tid < 128) {
        unsigned long long k1 = smk[tid * 4];
        float v2 = smv[tid * 4];
        #pragma unroll
        for (int w = 1; w < 4; ++w) t2merge(k1, v2, smk[tid * 4 + w], smv[tid * 4 + w]);
        g_partk[(size_t)(p0 + tid) * 4 + kc] = k1;
        g_partv[(size_t)(p0 + tid) * 4 + kc] = v2;
    }
}

// --------------------------------------------------------------------------
// Finalize: global top-2 across 4 chunks; write approx answer; enqueue
// tight-margin pixels for exact rescue.
// --------------------------------------------------------------------------
__global__ void finalize(float* __restrict__ out) {
    int p = blockIdx.x * 256 + threadIdx.x;
    unsigned long long k1 = g_partk[(size_t)p * 4];
    float v2 = g_partv[(size_t)p * 4];
    #pragma unroll
    for (int c = 1; c < 4; ++c)
        t2merge(k1, v2, g_partk[(size_t)p * 4 + c], g_partv[(size_t)p * 4 + c]);
    out[p] = (float)(int)(unsigned)(k1 & 0xFFFFFFFFULL);
    if (v2 - key_val(k1) < RESCUE_T) {
        int s = atomicAdd(&g_count, 1);
        g_queue[s] = p;
    }
}

// --------------------------------------------------------------------------
// Rescue: exact fp32 re-evaluation of all 512 codes for flagged pixels.
// 16 pixels per block batch; centers streamed via coalesced centT rows.
// --------------------------------------------------------------------------
__global__ __launch_bounds__(256, 2)
void rescue(const float* __restrict__ x, float* __restrict__ out) {
    __shared__ float xs[16][512];
    __shared__ unsigned long long best[16];
    const int t = threadIdx.x;
    const int cnt = g_count;

    for (int base = blockIdx.x * 16; base < cnt; base += 256 * 16) {
        const int nv = min(16, cnt - base);
        if (t < 16) best[t] = ~0ULL;
        // gather x vectors
        for (int i = 0; i < nv; ++i) {
            int p = g_queue[base + i];
            int b = p >> 12, hw = p & 4095;
            const float* src = x + (size_t)b * NC * NHW + hw;
            xs[i][t]       = src[(size_t)t * NHW];
            xs[i][t + 256] = src[(size_t)(t + 256) * NHW];
        }
        __syncthreads();

        float a0[16], a1[16];
        #pragma unroll
        for (int i = 0; i < 16; ++i) { a0[i] = 0.0f; a1[i] = 0.0f; }
        const float cq0 = g_csq[t], cq1 = g_csq[t + 256];

        #pragma unroll 4
        for (int cc = 0; cc < 512; ++cc) {
            float c0v = g_centT[cc * NK + t];
            float c1v = g_centT[cc * NK + t + 256];
            #pragma unroll
            for (int i = 0; i < 16; ++i) {
                float xv = xs[i][cc];
                a0[i] = fmaf(xv, c0v, a0[i]);
                a1[i] = fmaf(xv, c1v, a1[i]);
            }
        }
        #pragma unroll
        for (int i = 0; i < 16; ++i) {
            if (i < nv) {
                unsigned long long e0 = enc_key(fmaf(-2.0f, a0[i], cq0), t);
                unsigned long long e1 = enc_key(fmaf(-2.0f, a1[i], cq1), t + 256);
                atomicMin(&best[i], e0 < e1 ? e0 : e1);
            }
        }
        __syncthreads();
        if (t < nv)
            out[g_queue[base + t]] =
                (float)(int)(unsigned)(best[t] & 0xFFFFFFFFULL);
        __syncthreads();
    }
}

// --------------------------------------------------------------------------
// Launch
// --------------------------------------------------------------------------
extern "C" void kernel_launch(void* const* d_in, const int* in_sizes, int n_in,
                              void* d_out, int out_size) {
    const float* x    = (const float*)d_in[0];
    const float* cent = (const float*)d_in[1];
    if (n_in >= 2 && in_sizes[0] < in_sizes[1]) {
        const float* t = x; x = cent; cent = t;
    }

    cudaFuncSetAttribute(hmma_top2,
                         cudaFuncAttributeMaxDynamicSharedMemorySize, SMEM_TOTAL);

    convert_c<<<(NK * NC + 255) / 256, 256>>>(cent);
    csq_kernel<<<NK, 128>>>(cent);
    dim3 tg(NP / 64, NC / 64);
    convert_x<<<tg, 256>>>(x);
    hmma_top2<<<NP / 128 * 4, 256, SMEM_TOTAL>>>();
    finalize<<<NP / 256, 256>>>((float*)d_out);
    rescue<<<256, 256>>>(x, (float*)d_out);
    (void)out_size;
}

// round 10
// speedup vs baseline: 1.4362x; 1.0439x over previous
#include <cuda_runtime.h>
#include <cuda_fp16.h>
#include <cstdint>

#define NB  16
#define NC  512
#define NK  512
#define NHW 4096
#define NP  (NB * NHW)   // 65536 pixels

#define RESCUE_T 0.2f

// --------------------------------------------------------------------------
// Allocation-free scratch
// --------------------------------------------------------------------------
__device__ __half g_x16[(size_t)NP * NC];   // x fp16, [p][c] K-major
__device__ __half g_c16[NK * NC];           // centers fp16 [k][c]
__device__ float  g_centT[NC * NK];         // centers fp32 transposed [c][k]
__device__ float  g_csq[NK];
__device__ unsigned long long g_partk[(size_t)NP * 4];
__device__ float              g_partv[(size_t)NP * 4];
__device__ int g_count;
__device__ int g_queue[NP];

// --------------------------------------------------------------------------
// Helpers
// --------------------------------------------------------------------------
__device__ __forceinline__ uint32_t smem_u32(const void* p) {
    uint32_t a;
    asm("{ .reg .u64 t; cvta.to.shared.u64 t, %1; cvt.u32.u64 %0, t; }"
        : "=r"(a) : "l"(p));
    return a;
}
__device__ __forceinline__ unsigned long long enc_key(float v, int k) {
    unsigned u = __float_as_uint(v);
    u = (u & 0x80000000u) ? ~u : (u | 0x80000000u);
    return ((unsigned long long)u << 32) | (unsigned)k;
}
__device__ __forceinline__ float key_val(unsigned long long key) {
    unsigned u = (unsigned)(key >> 32);
    unsigned b = (u & 0x80000000u) ? (u & 0x7FFFFFFFu) : ~u;
    return __uint_as_float(b);
}
__device__ __forceinline__ void t2merge(unsigned long long& k1, float& v2,
                                        unsigned long long ok1, float ov2) {
    if (ok1 < k1) { v2 = fminf(key_val(k1), ov2); k1 = ok1; }
    else          { v2 = fminf(v2, key_val(ok1)); }
}
__device__ __forceinline__ void ldmx4(uint32_t* r, uint32_t addr) {
    asm volatile("ldmatrix.sync.aligned.m8n8.x4.shared.b16 {%0,%1,%2,%3}, [%4];"
                 : "=r"(r[0]), "=r"(r[1]), "=r"(r[2]), "=r"(r[3]) : "r"(addr));
}
__device__ __forceinline__ void mma16816(float* d, const uint32_t* a,
                                         uint32_t b0, uint32_t b1) {
    asm volatile(
        "mma.sync.aligned.m16n8k16.row.col.f32.f16.f16.f32 "
        "{%0,%1,%2,%3}, {%4,%5,%6,%7}, {%8,%9}, {%0,%1,%2,%3};"
        : "+f"(d[0]), "+f"(d[1]), "+f"(d[2]), "+f"(d[3])
        : "r"(a[0]), "r"(a[1]), "r"(a[2]), "r"(a[3]), "r"(b0), "r"(b1));
}

// --------------------------------------------------------------------------
// Prep kernels
// --------------------------------------------------------------------------
__global__ void convert_c(const float* __restrict__ cent) {
    int idx = blockIdx.x * 256 + threadIdx.x;
    if (idx == 0) g_count = 0;
    if (idx < NK * NC) {
        float f = cent[idx];
        g_c16[idx] = __float2half_rn(f);
        int k = idx >> 9, c = idx & 511;
        g_centT[c * NK + k] = f;
    }
}

__global__ void csq_kernel(const float* __restrict__ cent) {
    __shared__ double red[128];
    const int k = blockIdx.x;
    const int t = threadIdx.x;
    double s = 0.0;
    #pragma unroll
    for (int i = 0; i < 4; ++i) {
        double v = (double)cent[k * NC + t + i * 128];
        s += v * v;
    }
    red[t] = s;
    __syncthreads();
    for (int off = 64; off > 0; off >>= 1) {
        if (t < off) red[t] += red[t + off];
        __syncthreads();
    }
    if (t == 0) g_csq[k] = (float)red[0];
}

// x (B,C,H,W) fp32 -> [p][c] fp16 via smem transpose; coalesced 16B+ writes
__global__ void convert_x(const float* __restrict__ x) {
    __shared__ float s[64][65];
    const int p0 = blockIdx.x * 64;
    const int c0 = blockIdx.y * 64;
    const int b   = p0 >> 12;
    const int hw0 = p0 & 4095;
    const int t = threadIdx.x;
    const float* src = x + (size_t)b * NC * NHW + hw0;

    #pragma unroll
    for (int i = 0; i < 4; ++i) {
        int cl = i * 16 + (t >> 4);
        int pl = (t & 15) * 4;
        float4 v = *reinterpret_cast<const float4*>(src + (size_t)(c0 + cl) * NHW + pl);
        s[cl][pl] = v.x; s[cl][pl + 1] = v.y; s[cl][pl + 2] = v.z; s[cl][pl + 3] = v.w;
    }
    __syncthreads();

    // one item per thread: pixel = t>>2 (0..63), 16 channels = (t&3)*16
    {
        const int pl  = t >> 2;
        const int c16 = (t & 3) << 4;
        unsigned u[8];
        #pragma unroll
        for (int j = 0; j < 8; ++j) {
            __half2 h = __halves2half2(__float2half_rn(s[c16 + j * 2][pl]),
                                       __float2half_rn(s[c16 + j * 2 + 1][pl]));
            u[j] = *reinterpret_cast<unsigned*>(&h);
        }
        __half* dst = &g_x16[(size_t)(p0 + pl) * NC + c0 + c16];
        *reinterpret_cast<uint4*>(dst)     = make_uint4(u[0], u[1], u[2], u[3]);
        *reinterpret_cast<uint4*>(dst + 8) = make_uint4(u[4], u[5], u[6], u[7]);
    }
}

// --------------------------------------------------------------------------
// Smem: 4 stages x 16 KB (A 8 KB + B 8 KB), 64 B rows, XOR swizzle.
// Then csq (512 B) + top2 key (4 KB) + v2 (2 KB).
// --------------------------------------------------------------------------
#define STG_BYTES 16384
#define B_OFF     8192
#define OFF_CSQ   65536
#define OFF_K2    66048
#define OFF_V2    70144
#define SMEM_TOTAL 72192

// --------------------------------------------------------------------------
// Main GEMM: CTA = 128 px x 128 codes (grid 2048 = 512 groups x 4 chunks).
// Fully unrolled 16-iter mainloop: all ldmatrix/cp.async addresses are
// base-register + compile-time immediate. 4-stage cp.async ring, 1 bar/iter.
// --------------------------------------------------------------------------
__global__ __launch_bounds__(256, 2)
void hmma_top2() {
    extern __shared__ __align__(1024) char smem[];
    const uint32_t sb = smem_u32(smem);
    const int tid  = threadIdx.x;
    const int lane = tid & 31;
    const int wid  = tid >> 5;
    const int wm   = wid >> 2;
    const int wn   = wid & 3;

    const int grp = blockIdx.x >> 2;
    const int kc  = blockIdx.x & 3;
    const int p0  = grp * 128;

    float* cs = (float*)(smem + OFF_CSQ);
    if (tid < 128) cs[tid] = g_csq[kc * 128 + tid];

    // ---- precomputed loader state: 4 src pointers + 4 dst offsets ----
    const char* srcp[4];
    uint32_t dsto[4];
    #pragma unroll
    for (int u = 0; u < 4; ++u) {
        int q   = tid + (u << 8);
        int ab  = q >> 9;
        int row = (q >> 2) & 127;
        int j   = q & 3;
        srcp[u] = ab
            ? (const char*)(g_c16 + (size_t)(kc * 128 + row) * NC + j * 8)
            : (const char*)(g_x16 + (size_t)(p0 + row) * NC + j * 8);
        dsto[u] = sb + ab * B_OFF + row * 64 + ((j ^ ((row >> 1) & 3)) << 4);
    }

    // ---- precomputed ldmatrix base addresses (stage 0) ----
    const int rA  = wm * 64 + (lane & 15);
    const int swA = (rA >> 1) & 3;
    const int rB  = wn * 32 + (lane & 15);
    const int swB = (rB >> 1) & 3;
    const int khalf = lane >> 4;
    uint32_t aadr[2][4], badr[2][2];
    #pragma unroll
    for (int ks = 0; ks < 2; ++ks) {
        const int jj = ks * 2 + khalf;
        #pragma unroll
        for (int mt = 0; mt < 4; ++mt)
            aadr[ks][mt] = sb + (rA + mt * 16) * 64 + ((jj ^ swA) << 4);
        #pragma unroll
        for (int nt = 0; nt < 2; ++nt)
            badr[ks][nt] = sb + B_OFF + (rB + nt * 16) * 64 + ((jj ^ swB) << 4);
    }

    float acc[4][4][4];
    #pragma unroll
    for (int m = 0; m < 4; ++m)
        #pragma unroll
        for (int n = 0; n < 4; ++n)
            #pragma unroll
            for (int r = 0; r < 4; ++r) acc[m][n][r] = 0.0f;

    // ---- pipeline ----
    #pragma unroll
    for (int i = 0; i < 3; ++i) {       // prologue loads 0,1,2
        #pragma unroll
        for (int u = 0; u < 4; ++u)
            asm volatile("cp.async.cg.shared.global [%0], [%1], 16;"
                :: "r"(dsto[u] + (i & 3) * STG_BYTES), "l"(srcp[u] + i * 64)
                : "memory");
        asm volatile("cp.async.commit_group;" ::: "memory");
    }

    #pragma unroll
    for (int i = 0; i < 16; ++i) {
        if (i < 14)       asm volatile("cp.async.wait_group 2;" ::: "memory");
        else if (i == 14) asm volatile("cp.async.wait_group 1;" ::: "memory");
        else              asm volatile("cp.async.wait_group 0;" ::: "memory");
        __syncthreads();
        if (i + 3 < 16) {
            #pragma unroll
            for (int u = 0; u < 4; ++u)
                asm volatile("cp.async.cg.shared.global [%0], [%1], 16;"
                    :: "r"(dsto[u] + ((i + 3) & 3) * STG_BYTES),
                       "l"(srcp[u] + (i + 3) * 64)
                    : "memory");
            asm volatile("cp.async.commit_group;" ::: "memory");
        }
        const uint32_t S = (i & 3) * STG_BYTES;   // compile-time per body
        #pragma unroll
        for (int ks = 0; ks < 2; ++ks) {
            uint32_t ah[4][4];
            #pragma unroll
            for (int mt = 0; mt < 4; ++mt)
                ldmx4(ah[mt], aadr[ks][mt] + S);
            #pragma unroll
            for (int nt = 0; nt < 2; ++nt) {
                uint32_t bf[4];
                ldmx4(bf, badr[ks][nt] + S);
                #pragma unroll
                for (int sub = 0; sub < 2; ++sub) {
                    const int nn = nt * 2 + sub;
                    #pragma unroll
                    for (int mt = 0; mt < 4; ++mt)
                        mma16816(acc[mt][nn], ah[mt], bf[sub], bf[sub + 2]);
                }
            }
        }
    }

    // ---- epilogue: per-row top-2 in registers, merge via shfl ----
    unsigned long long* smk = (unsigned long long*)(smem + OFF_K2);
    float*              smv = (float*)(smem + OFF_V2);
    const int r4 = lane >> 2, c2 = (lane & 3) << 1;

    #pragma unroll
    for (int mt = 0; mt < 4; ++mt) {
        unsigned long long k1a = ~0ULL, k1b = ~0ULL;
        float v2a = 3.0e38f, v2b = 3.0e38f;
        const int row0 = wm * 64 + mt * 16 + r4;
        #pragma unroll
        for (int nn = 0; nn < 4; ++nn) {
            #pragma unroll
            for (int cc = 0; cc < 2; ++cc) {
                const int col = wn * 32 + nn * 8 + c2 + cc;
                const int kg  = kc * 128 + col;
                float va = fmaf(-2.0f, acc[mt][nn][cc], cs[col]);
                float vb = fmaf(-2.0f, acc[mt][nn][cc + 2], cs[col]);
                unsigned long long ea = enc_key(va, kg);
                unsigned long long eb = enc_key(vb, kg);
                if (ea < k1a) { v2a = fminf(v2a, key_val(k1a)); k1a = ea; }
                else           v2a = fminf(v2a, va);
                if (eb < k1b) { v2b = fminf(v2b, key_val(k1b)); k1b = eb; }
                else           v2b = fminf(v2b, vb);
            }
        }
        #pragma unroll
        for (int d = 1; d <= 2; d <<= 1) {
            unsigned long long oka = __shfl_xor_sync(0xFFFFFFFFu, k1a, d);
            float ova              = __shfl_xor_sync(0xFFFFFFFFu, v2a, d);
            t2merge(k1a, v2a, oka, ova);
            unsigned long long okb = __shfl_xor_sync(0xFFFFFFFFu, k1b, d);
            float ovb              = __shfl_xor_sync(0xFFFFFFFFu, v2b, d);
            t2merge(k1b, v2b, okb, ovb);
        }
        if ((lane & 3) == 0) {
            smk[row0 * 4 + wn] = k1a;  smv[row0 * 4 + wn] = v2a;
            smk[(row0 + 8) * 4 + wn] = k1b;  smv[(row0 + 8) * 4 + wn] = v2b;
        }
    }
    __syncthreads();

    if (tid < 128) {
        unsigned long long k1 = smk[tid * 4];
        float v2 = smv[tid * 4];
        #pragma unroll
        for (int w = 1; w < 4; ++w) t2merge(k1, v2, smk[tid * 4 + w], smv[tid * 4 + w]);
        g_partk[(size_t)(p0 + tid) * 4 + kc] = k1;
        g_partv[(size_t)(p0 + tid) * 4 + kc] = v2;
    }
}

// --------------------------------------------------------------------------
// Finalize: global top-2 across chunks; enqueue tight margins for rescue.
// --------------------------------------------------------------------------
__global__ void finalize(float* __restrict__ out) {
    int p = blockIdx.x * 256 + threadIdx.x;
    unsigned long long k1 = g_partk[(size_t)p * 4];
    float v2 = g_partv[(size_t)p * 4];
    #pragma unroll
    for (int c = 1; c < 4; ++c)
        t2merge(k1, v2, g_partk[(size_t)p * 4 + c], g_partv[(size_t)p * 4 + c]);
    out[p] = (float)(int)(unsigned)(k1 & 0xFFFFFFFFULL);
    if (v2 - key_val(k1) < RESCUE_T) {
        int s = atomicAdd(&g_count, 1);
        g_queue[s] = p;
    }
}

// --------------------------------------------------------------------------
// Rescue: exact fp32 re-evaluation of all 512 codes for flagged pixels.
// --------------------------------------------------------------------------
__global__ __launch_bounds__(256, 2)
void rescue(const float* __restrict__ x, float* __restrict__ out) {
    __shared__ float xs[16][512];
    __shared__ unsigned long long best[16];
    const int t = threadIdx.x;
    const int cnt = g_count;

    for (int base = blockIdx.x * 16; base < cnt; base += 256 * 16) {
        const int nv = min(16, cnt - base);
        if (t < 16) best[t] = ~0ULL;
        for (int i = 0; i < nv; ++i) {
            int p = g_queue[base + i];
            int b = p >> 12, hw = p & 4095;
            const float* src = x + (size_t)b * NC * NHW + hw;
            xs[i][t]       = src[(size_t)t * NHW];
            xs[i][t + 256] = src[(size_t)(t + 256) * NHW];
        }
        __syncthreads();

        float a0[16], a1[16];
        #pragma unroll
        for (int i = 0; i < 16; ++i) { a0[i] = 0.0f; a1[i] = 0.0f; }
        const float cq0 = g_csq[t], cq1 = g_csq[t + 256];

        #pragma unroll 4
        for (int cc = 0; cc < 512; ++cc) {
            float c0v = g_centT[cc * NK + t];
            float c1v = g_centT[cc * NK + t + 256];
            #pragma unroll
            for (int i = 0; i < 16; ++i) {
                float xv = xs[i][cc];
                a0[i] = fmaf(xv, c0v, a0[i]);
                a1[i] = fmaf(xv, c1v, a1[i]);
            }
        }
        #pragma unroll
        for (int i = 0; i < 16; ++i) {
            if (i < nv) {
                unsigned long long e0 = enc_key(fmaf(-2.0f, a0[i], cq0), t);
                unsigned long long e1 = enc_key(fmaf(-2.0f, a1[i], cq1), t + 256);
                atomicMin(&best[i], e0 < e1 ? e0 : e1);
            }
        }
        __syncthreads();
        if (t < nv)
            out[g_queue[base + t]] =
                (float)(int)(unsigned)(best[t] & 0xFFFFFFFFULL);
        __syncthreads();
    }
}

// --------------------------------------------------------------------------
// Launch
// --------------------------------------------------------------------------
extern "C" void kernel_launch(void* const* d_in, const int* in_sizes, int n_in,
                              void* d_out, int out_size) {
    const float* x    = (const float*)d_in[0];
    const float* cent = (const float*)d_in[1];
    if (n_in >= 2 && in_sizes[0] < in_sizes[1]) {
        const float* t = x; x = cent; cent = t;
    }

    cudaFuncSetAttribute(hmma_top2,
                         cudaFuncAttributeMaxDynamicSharedMemorySize, SMEM_TOTAL);

    convert_c<<<(NK * NC + 255) / 256, 256>>>(cent);
    csq_kernel<<<NK, 128>>>(cent);
    dim3 tg(NP / 64, NC / 64);
    convert_x<<<tg, 256>>>(x);
    hmma_top2<<<NP / 128 * 4, 256, SMEM_TOTAL>>>();
    finalize<<<NP / 256, 256>>>((float*)d_out);
    rescue<<<256, 256>>>(x, (float*)d_out);
    (void)out_size;
}